// round 2
// baseline (speedup 1.0000x reference)
#include <cuda_runtime.h>

// Problem constants
#define NB 16
#define LL 512
#define EE 256
#define FF 256
#define MM 4096
#define OUT_ELEMS (NB * MM * EE)   // 16777216

// ---------------- scratch (no allocations allowed) ----------------
__device__ float g_h1[NB * LL * FF];     // 8 MB intermediate (post conv1+LN+relu)
__device__ float g_w1t[768 * FF];        // conv1 weights transposed: [(k*E+e)][f]
__device__ float g_w2t[768 * FF];        // conv2 weights transposed
__device__ int   g_idx[NB * MM];         // t -> token index (or -1)

// ---------------- f32x2 helpers (sm_100+ packed fp32) ----------------
__device__ __forceinline__ unsigned long long pk2(float lo, float hi) {
    unsigned long long r;
    asm("mov.b64 %0, {%1, %2};" : "=l"(r) : "f"(lo), "f"(hi));
    return r;
}
__device__ __forceinline__ void unpk2(float& lo, float& hi, unsigned long long v) {
    asm("mov.b64 {%0, %1}, %2;" : "=f"(lo), "=f"(hi) : "l"(v));
}
__device__ __forceinline__ unsigned long long fma2(unsigned long long a,
                                                   unsigned long long b,
                                                   unsigned long long c) {
    unsigned long long d;
    asm("fma.rn.f32x2 %0, %1, %2, %3;" : "=l"(d) : "l"(a), "l"(b), "l"(c));
    return d;
}

// ---------------- weight transpose: w[f][e][k] -> wt[(k*256+e)][f] ----------------
__global__ void transpose_w_kernel(const float* __restrict__ w1,
                                   const float* __restrict__ w2) {
    int f = blockIdx.x;                  // 0..255
    const float* w  = blockIdx.y ? w2 : w1;
    float*       wt = blockIdx.y ? g_w2t : g_w1t;
    const float* wr = w + f * 768;       // row f: [e][k] contiguous
    for (int i = threadIdx.x; i < 768; i += blockDim.x) {
        int e = i / 3;
        int k = i - e * 3;
        wt[(k * 256 + e) * 256 + f] = wr[i];
    }
}

// ---------------- build idx map: scan durations, scatter intervals ----------------
__global__ void build_idx_kernel(const int* __restrict__ target) {
    int n = blockIdx.x;
    int t = threadIdx.x;                 // 512 threads
    __shared__ int s[512];
    int d = target[n * LL + t];
    s[t] = d;
    __syncthreads();
    // Hillis-Steele inclusive scan
    for (int off = 1; off < 512; off <<= 1) {
        int v = (t >= off) ? s[t - off] : 0;
        __syncthreads();
        s[t] += v;
        __syncthreads();
    }
    int cum = s[t];
    int start = cum - d;
    for (int i = t; i < MM; i += 512) g_idx[n * MM + i] = -1;
    __syncthreads();
    for (int u = start; u < cum; ++u) g_idx[n * MM + u] = t;
}

// ---------------- gather: out[n,t,:] = x[n,idx,:] or 0 ----------------
__global__ void gather_kernel(const float* __restrict__ x, float* __restrict__ out) {
    int warp = threadIdx.x >> 5;
    int lane = threadIdx.x & 31;
    int row  = blockIdx.x * 8 + warp;    // 0 .. 65535
    int n    = row >> 12;
    int j    = g_idx[row];
    float4 v0 = make_float4(0.f, 0.f, 0.f, 0.f), v1 = v0;
    if (j >= 0) {
        const float4* src = reinterpret_cast<const float4*>(x + (size_t)(n * LL + j) * EE);
        v0 = src[lane * 2];
        v1 = src[lane * 2 + 1];
    }
    float4* dst = reinterpret_cast<float4*>(out + (size_t)row * EE);
    dst[lane * 2]     = v0;
    dst[lane * 2 + 1] = v1;
}

// ---------------- fused conv1d(k=3) + bias + LayerNorm + ReLU (+ dur dot) ----------
// Block: 256 threads, 64 L-rows x 256 F cols.  8 warps, 8 rows/warp.
// Lane owns cols {4*lane..4*lane+3} U {128+4*lane..131+4*lane} (conflict-free LDS.128).
// Accumulators are f32x2 pairs over adjacent columns.
template <int SECOND>
__global__ void __launch_bounds__(256) conv_ln_kernel(
    const float* __restrict__ xin,
    const float* __restrict__ bias,
    const float* __restrict__ gamma,
    const float* __restrict__ beta,
    const float* __restrict__ lw,
    const float* __restrict__ lbp,
    float* __restrict__ durout)
{
    __shared__ __align__(16) float Xs[66 * 32];   // rows l0-1 .. l0+64, 32 E-cols
    __shared__ __align__(16) float Ws[32 * 256];  // 32 K-rows x 256 F

    const float* in = SECOND ? g_h1 : xin;
    const float* wt = SECOND ? g_w2t : g_w1t;

    int tid  = threadIdx.x;
    int n    = blockIdx.x >> 3;
    int l0   = (blockIdx.x & 7) << 6;
    int warp = tid >> 5;
    int lane = tid & 31;
    int r0   = warp << 3;        // first of 8 rows
    int c4a  = lane << 2;        // cols c4a..c4a+3
    int c4b  = 128 + c4a;        // cols c4b..c4b+3
    const float* inb = in + (size_t)n * LL * 256;

    unsigned long long acc[8][4];
#pragma unroll
    for (int i = 0; i < 8; ++i)
#pragma unroll
        for (int p = 0; p < 4; ++p) acc[i][p] = 0ULL;

    for (int ec = 0; ec < 8; ++ec) {
        __syncthreads();  // previous iteration done with Xs
        for (int i = tid; i < 66 * 32; i += 256) {
            int r  = i >> 5;
            int c  = i & 31;
            int gl = l0 + r - 1;
            float v = 0.f;
            if (gl >= 0 && gl < LL) v = inb[gl * 256 + (ec << 5) + c];
            Xs[i] = v;
        }
        for (int kk = 0; kk < 3; ++kk) {
            __syncthreads();  // Xs ready / Ws consumers done
            {
                const float4* src = reinterpret_cast<const float4*>(
                    wt + (size_t)(kk * 256 + (ec << 5)) * 256);
                float4* dst = reinterpret_cast<float4*>(Ws);
#pragma unroll
                for (int i = 0; i < 8; ++i) dst[tid + (i << 8)] = src[tid + (i << 8)];
            }
            __syncthreads();
#pragma unroll 8
            for (int k = 0; k < 32; ++k) {
                const float* wrow = Ws + (k << 8);
                ulonglong2 wa = *reinterpret_cast<const ulonglong2*>(wrow + c4a);
                ulonglong2 wb = *reinterpret_cast<const ulonglong2*>(wrow + c4b);
                const float* xcol = Xs + ((r0 + kk) << 5) + k;
#pragma unroll
                for (int i = 0; i < 8; ++i) {
                    float xv = xcol[i << 5];
                    unsigned long long xp = pk2(xv, xv);
                    acc[i][0] = fma2(xp, wa.x, acc[i][0]);
                    acc[i][1] = fma2(xp, wa.y, acc[i][1]);
                    acc[i][2] = fma2(xp, wb.x, acc[i][2]);
                    acc[i][3] = fma2(xp, wb.y, acc[i][3]);
                }
            }
        }
    }

    // ---------------- epilogue: bias + LN + ReLU (+ dur dot) ----------------
    float4 ba = *reinterpret_cast<const float4*>(bias + c4a);
    float4 bb = *reinterpret_cast<const float4*>(bias + c4b);
    float4 ga = *reinterpret_cast<const float4*>(gamma + c4a);
    float4 gb = *reinterpret_cast<const float4*>(gamma + c4b);
    float4 ea = *reinterpret_cast<const float4*>(beta + c4a);
    float4 eb = *reinterpret_cast<const float4*>(beta + c4b);
    float4 la = make_float4(0.f, 0.f, 0.f, 0.f), lb = la;
    float linb = 0.f;
    if (SECOND) {
        la = *reinterpret_cast<const float4*>(lw + c4a);
        lb = *reinterpret_cast<const float4*>(lw + c4b);
        linb = *lbp;
    }

#pragma unroll
    for (int i = 0; i < 8; ++i) {
        float h[8];
        unpk2(h[0], h[1], acc[i][0]);
        unpk2(h[2], h[3], acc[i][1]);
        unpk2(h[4], h[5], acc[i][2]);
        unpk2(h[6], h[7], acc[i][3]);
        h[0] += ba.x; h[1] += ba.y; h[2] += ba.z; h[3] += ba.w;
        h[4] += bb.x; h[5] += bb.y; h[6] += bb.z; h[7] += bb.w;

        float s = 0.f, ss = 0.f;
#pragma unroll
        for (int j = 0; j < 8; ++j) { s += h[j]; ss += h[j] * h[j]; }
#pragma unroll
        for (int o = 16; o; o >>= 1) {
            s  += __shfl_xor_sync(0xffffffffu, s, o);
            ss += __shfl_xor_sync(0xffffffffu, ss, o);
        }
        float mu  = s * (1.f / 256.f);
        float var = ss * (1.f / 256.f) - mu * mu;
        float rs  = rsqrtf(var + 1e-5f);

        float y[8];
        y[0] = fmaxf(0.f, (h[0] - mu) * rs * ga.x + ea.x);
        y[1] = fmaxf(0.f, (h[1] - mu) * rs * ga.y + ea.y);
        y[2] = fmaxf(0.f, (h[2] - mu) * rs * ga.z + ea.z);
        y[3] = fmaxf(0.f, (h[3] - mu) * rs * ga.w + ea.w);
        y[4] = fmaxf(0.f, (h[4] - mu) * rs * gb.x + eb.x);
        y[5] = fmaxf(0.f, (h[5] - mu) * rs * gb.y + eb.y);
        y[6] = fmaxf(0.f, (h[6] - mu) * rs * gb.z + eb.z);
        y[7] = fmaxf(0.f, (h[7] - mu) * rs * gb.w + eb.w);

        int row = l0 + r0 + i;
        if (!SECOND) {
            float* o = g_h1 + (size_t)(n * LL + row) * 256;
            *reinterpret_cast<float4*>(o + c4a) = make_float4(y[0], y[1], y[2], y[3]);
            *reinterpret_cast<float4*>(o + c4b) = make_float4(y[4], y[5], y[6], y[7]);
        } else {
            float d = y[0] * la.x + y[1] * la.y + y[2] * la.z + y[3] * la.w
                    + y[4] * lb.x + y[5] * lb.y + y[6] * lb.z + y[7] * lb.w;
#pragma unroll
            for (int o = 16; o; o >>= 1) d += __shfl_xor_sync(0xffffffffu, d, o);
            if (lane == 0) durout[n * LL + row] = fmaxf(0.f, d + linb);
        }
    }
}

// ---------------- launch ----------------
extern "C" void kernel_launch(void* const* d_in, const int* in_sizes, int n_in,
                              void* d_out, int out_size) {
    const float* x      = (const float*)d_in[0];
    const float* c1w    = (const float*)d_in[1];
    const float* c1b    = (const float*)d_in[2];
    const float* l1g    = (const float*)d_in[3];
    const float* l1b    = (const float*)d_in[4];
    const float* c2w    = (const float*)d_in[5];
    const float* c2b    = (const float*)d_in[6];
    const float* l2g    = (const float*)d_in[7];
    const float* l2b    = (const float*)d_in[8];
    const float* lw     = (const float*)d_in[9];
    const float* lb     = (const float*)d_in[10];
    const int*   target = (const int*)d_in[11];
    float* out = (float*)d_out;

    transpose_w_kernel<<<dim3(256, 2), 256>>>(c1w, c2w);
    build_idx_kernel<<<16, 512>>>(target);
    conv_ln_kernel<0><<<128, 256>>>(x, c1b, l1g, l1b, lw, lb, nullptr);
    conv_ln_kernel<1><<<128, 256>>>(x, c2b, l2g, l2b, lw, lb, out + OUT_ELEMS);
    gather_kernel<<<NB * MM / 8, 256>>>(x, out);
}

// round 5
// speedup vs baseline: 1.6138x; 1.6138x over previous
#include <cuda_runtime.h>
#include <cuda_bf16.h>
#include <cstdint>

#define NB 16
#define LL 512
#define EE 256
#define FF 256
#define MM 4096
#define OUT_ELEMS (NB * MM * EE)   // 16777216
#define KTOT 768
#define NROWS (NB * LL)            // 8192
#define KC 64                      // K chunk (bf16)
#define NCHUNK (KTOT / KC)         // 12
#define PADK 72                    // padded row length (bf16) -> 144 B
#define ROWB (PADK * 2)            // 144 bytes

// ---------------- scratch (hi/lo bf16 planes for 3xBF16 compensation) --------
__device__ __nv_bfloat16 g_xh1[NROWS * KTOT];  // im2col(x) hi
__device__ __nv_bfloat16 g_xl1[NROWS * KTOT];  // im2col(x) lo
__device__ __nv_bfloat16 g_xh2[NROWS * KTOT];  // im2col(h1) hi
__device__ __nv_bfloat16 g_xl2[NROWS * KTOT];  // im2col(h1) lo
__device__ __nv_bfloat16 g_h1h[NROWS * FF];    // conv1 out hi
__device__ __nv_bfloat16 g_h1l[NROWS * FF];    // conv1 out lo
__device__ __nv_bfloat16 g_wh1[FF * KTOT];
__device__ __nv_bfloat16 g_wl1[FF * KTOT];
__device__ __nv_bfloat16 g_wh2[FF * KTOT];
__device__ __nv_bfloat16 g_wl2[FF * KTOT];
__device__ int           g_idx[NB * MM];

// ---------------- smem layout ----------------
#define ASZ   (128 * ROWB)             // 18432: A_hi rows 0-63, A_lo rows 64-127
#define BSZ   (512 * ROWB)             // 73728: B_hi rows 0-255, B_lo rows 256-511
#define STAGE (ASZ + BSZ)              // 92160
#define SM_PAR (2 * STAGE)             // 184320: bias|gamma|beta|lw
#define SM_TOTAL (SM_PAR + 4096)       // 188416

// ---------------- helpers ----------------
__device__ __forceinline__ uint32_t smem_u32(const void* p) {
    uint32_t a;
    asm("{ .reg .u64 t; cvta.to.shared.u64 t, %1; cvt.u32.u64 %0, t; }" : "=r"(a) : "l"(p));
    return a;
}
__device__ __forceinline__ void cp16(uint32_t dst, const void* src) {
    asm volatile("cp.async.cg.shared.global [%0], [%1], 16;" :: "r"(dst), "l"(src));
}
#define CP_COMMIT() asm volatile("cp.async.commit_group;" ::: "memory")
template <int N>
__device__ __forceinline__ void cp_wait() {
    asm volatile("cp.async.wait_group %0;" :: "n"(N) : "memory");
}
__device__ __forceinline__ uint32_t lds32(uint32_t a) {
    uint32_t v;
    asm volatile("ld.shared.b32 %0, [%1];" : "=r"(v) : "r"(a));
    return v;
}
__device__ __forceinline__ void mma_bf16(float* d, uint32_t a0, uint32_t a1,
                                         uint32_t a2, uint32_t a3,
                                         uint32_t b0, uint32_t b1) {
    asm volatile(
        "mma.sync.aligned.m16n8k16.row.col.f32.bf16.bf16.f32 "
        "{%0,%1,%2,%3}, {%4,%5,%6,%7}, {%8,%9}, {%0,%1,%2,%3};"
        : "+f"(d[0]), "+f"(d[1]), "+f"(d[2]), "+f"(d[3])
        : "r"(a0), "r"(a1), "r"(a2), "r"(a3), "r"(b0), "r"(b1));
}
// split fp32 -> (hi, lo) bf16
__device__ __forceinline__ void split_bf16(float v, __nv_bfloat16& hi, __nv_bfloat16& lo) {
    hi = __float2bfloat16(v);
    lo = __float2bfloat16(v - __bfloat162float(hi));
}
__device__ __forceinline__ uint32_t pack2h(float a, float b) {
    __nv_bfloat162 p = __floats2bfloat162_rn(a, b);
    return *reinterpret_cast<uint32_t*>(&p);
}

// ---------------- weight prep: w[f][e][k] fp32 -> hi/lo [f][k*256+e] ---------
__global__ void prep_w_kernel(const float* __restrict__ w1, const float* __restrict__ w2) {
    int f = blockIdx.x;
    const float* w = blockIdx.y ? w2 : w1;
    __nv_bfloat16* wh = blockIdx.y ? g_wh2 : g_wh1;
    __nv_bfloat16* wl = blockIdx.y ? g_wl2 : g_wl1;
    int e = threadIdx.x;
#pragma unroll
    for (int k = 0; k < 3; ++k) {
        __nv_bfloat16 hi, lo;
        split_bf16(w[f * KTOT + e * 3 + k], hi, lo);
        wh[f * KTOT + k * 256 + e] = hi;
        wl[f * KTOT + k * 256 + e] = lo;
    }
}

// ---------------- im2col: rows -> hi/lo planes [row][k*256+e], zero halo -----
// SRC=0: from x (fp32);  SRC=1: from g_h1h/g_h1l (bf16 planes)
template <int SRC>
__global__ void __launch_bounds__(256) im2col_kernel(const float* __restrict__ x) {
    int warp = threadIdx.x >> 5, lane = threadIdx.x & 31;
    int row = blockIdx.x * 8 + warp;
    int n = row >> 9, l = row & 511;
    int e0 = lane * 8;
    __nv_bfloat16* dh = SRC ? g_xh2 : g_xh1;
    __nv_bfloat16* dl = SRC ? g_xl2 : g_xl1;
#pragma unroll
    for (int k = 0; k < 3; ++k) {
        int sl = l + k - 1;
        uint4 vh = make_uint4(0u, 0u, 0u, 0u), vl = vh;
        if (sl >= 0 && sl < LL) {
            if (SRC == 0) {
                const float* xr = x + ((size_t)(n * LL + sl) * EE + e0);
                uint32_t* ph = reinterpret_cast<uint32_t*>(&vh);
                uint32_t* pl = reinterpret_cast<uint32_t*>(&vl);
#pragma unroll
                for (int q = 0; q < 4; ++q) {
                    __nv_bfloat16 h0, l0, h1, l1;
                    split_bf16(xr[2 * q], h0, l0);
                    split_bf16(xr[2 * q + 1], h1, l1);
                    ph[q] = ((uint32_t)*reinterpret_cast<uint16_t*>(&h1) << 16) |
                            *reinterpret_cast<uint16_t*>(&h0);
                    pl[q] = ((uint32_t)*reinterpret_cast<uint16_t*>(&l1) << 16) |
                            *reinterpret_cast<uint16_t*>(&l0);
                }
            } else {
                size_t off = (size_t)(n * LL + sl) * FF + e0;
                vh = *reinterpret_cast<const uint4*>(g_h1h + off);
                vl = *reinterpret_cast<const uint4*>(g_h1l + off);
            }
        }
        size_t doff = (size_t)row * KTOT + k * 256 + e0;
        *reinterpret_cast<uint4*>(dh + doff) = vh;
        *reinterpret_cast<uint4*>(dl + doff) = vl;
    }
}

// ---------------- build idx map ----------------
__global__ void build_idx_kernel(const int* __restrict__ target) {
    int n = blockIdx.x, t = threadIdx.x;
    __shared__ int s[512];
    int d = target[n * LL + t];
    s[t] = d;
    __syncthreads();
    for (int off = 1; off < 512; off <<= 1) {
        int v = (t >= off) ? s[t - off] : 0;
        __syncthreads();
        s[t] += v;
        __syncthreads();
    }
    int cum = s[t], start = cum - d;
    for (int i = t; i < MM; i += 512) g_idx[n * MM + i] = -1;
    __syncthreads();
    for (int u = start; u < cum; ++u) g_idx[n * MM + u] = t;
}

// ---------------- gather ----------------
__global__ void gather_kernel(const float* __restrict__ x, float* __restrict__ out) {
    int warp = threadIdx.x >> 5, lane = threadIdx.x & 31;
    int row = blockIdx.x * 8 + warp;
    int n = row >> 12;
    int j = g_idx[row];
    float4 v0 = make_float4(0.f, 0.f, 0.f, 0.f), v1 = v0;
    if (j >= 0) {
        const float4* src = reinterpret_cast<const float4*>(x + (size_t)(n * LL + j) * EE);
        v0 = src[lane * 2];
        v1 = src[lane * 2 + 1];
    }
    float4* dst = reinterpret_cast<float4*>(out + (size_t)row * EE);
    dst[lane * 2] = v0;
    dst[lane * 2 + 1] = v1;
}

// ---------------- 3xBF16 HMMA GEMM + fused LN/ReLU epilogue ------------------
// Y[8192,256] = X'[8192,768] @ Wb^T in compensated bf16 (fp32-grade).
// CTA: M=64, N=256. 8 warps (2m x 4n), warp tile 32x64.
template <int SECOND>
__global__ void __launch_bounds__(256) gemm_ln_kernel(
    const float* __restrict__ bias, const float* __restrict__ gamma,
    const float* __restrict__ beta, const float* __restrict__ lw,
    const float* __restrict__ lbp, float* __restrict__ durout)
{
    extern __shared__ char smem[];
    uint32_t sb = smem_u32(smem);
    int tid = threadIdx.x, wid = tid >> 5, lane = tid & 31;
    int m0 = blockIdx.x * 64;
    int wm = wid & 1, wn = wid >> 1;
    int g = lane >> 2, t = lane & 3;
    const __nv_bfloat16* Ah = SECOND ? g_xh2 : g_xh1;
    const __nv_bfloat16* Al = SECOND ? g_xl2 : g_xl1;
    const __nv_bfloat16* Bh = SECOND ? g_wh2 : g_wh1;
    const __nv_bfloat16* Bl = SECOND ? g_wl2 : g_wl1;

    {
        float* pp = reinterpret_cast<float*>(smem + SM_PAR);
        pp[tid] = bias[tid];
        pp[256 + tid] = gamma[tid];
        pp[512 + tid] = beta[tid];
        pp[768 + tid] = SECOND ? lw[tid] : 0.f;
    }

    auto issue_chunk = [&](int c, int buf) {
        uint32_t sa = sb + buf * STAGE;
        uint32_t sbm = sa + ASZ;
        size_t aoff = ((size_t)m0 * KTOT + c * KC) * 2;
        size_t boff = (size_t)c * KC * 2;
        const char* gAh = reinterpret_cast<const char*>(Ah) + aoff;
        const char* gAl = reinterpret_cast<const char*>(Al) + aoff;
        const char* gBh = reinterpret_cast<const char*>(Bh) + boff;
        const char* gBl = reinterpret_cast<const char*>(Bl) + boff;
#pragma unroll
        for (int i = 0; i < 2; ++i) {          // A_hi: 64 rows x 8 segs
            int lin = tid + (i << 8);
            int row = lin >> 3, seg = lin & 7;
            cp16(sa + row * ROWB + seg * 16, gAh + (size_t)row * 1536 + seg * 16);
        }
#pragma unroll
        for (int i = 0; i < 2; ++i) {          // A_lo -> smem rows 64..127
            int lin = tid + (i << 8);
            int row = lin >> 3, seg = lin & 7;
            cp16(sa + (64 + row) * ROWB + seg * 16, gAl + (size_t)row * 1536 + seg * 16);
        }
#pragma unroll
        for (int i = 0; i < 8; ++i) {          // B_hi: 256 rows x 8 segs
            int lin = tid + (i << 8);
            int row = lin >> 3, seg = lin & 7;
            cp16(sbm + row * ROWB + seg * 16, gBh + (size_t)row * 1536 + seg * 16);
        }
#pragma unroll
        for (int i = 0; i < 8; ++i) {          // B_lo -> smem rows 256..511
            int lin = tid + (i << 8);
            int row = lin >> 3, seg = lin & 7;
            cp16(sbm + (256 + row) * ROWB + seg * 16, gBl + (size_t)row * 1536 + seg * 16);
        }
        CP_COMMIT();
    };

    float acc[2][8][4];
#pragma unroll
    for (int mt = 0; mt < 2; ++mt)
#pragma unroll
        for (int nt = 0; nt < 8; ++nt)
#pragma unroll
            for (int q = 0; q < 4; ++q) acc[mt][nt][q] = 0.f;

    issue_chunk(0, 0);
    for (int c = 0; c < NCHUNK; ++c) {
        int buf = c & 1;
        if (c + 1 < NCHUNK) {
            issue_chunk(c + 1, buf ^ 1);
            cp_wait<1>();
        } else {
            cp_wait<0>();
        }
        __syncthreads();
        uint32_t abase = sb + buf * STAGE;
        uint32_t bbase = abase + ASZ;
#pragma unroll
        for (int ks = 0; ks < 4; ++ks) {
            int k0 = ks * 16;
            uint32_t bh[8][2], bl[8][2];
#pragma unroll
            for (int nt = 0; nt < 8; ++nt) {
                uint32_t ba = bbase + (wn * 64 + nt * 8 + g) * ROWB + (k0 + 2 * t) * 2;
                bh[nt][0] = lds32(ba);
                bh[nt][1] = lds32(ba + 16);
                bl[nt][0] = lds32(ba + 256 * ROWB);
                bl[nt][1] = lds32(ba + 256 * ROWB + 16);
            }
#pragma unroll
            for (int mt = 0; mt < 2; ++mt) {
                uint32_t ra = abase + (wm * 32 + mt * 16 + g) * ROWB + (k0 + 2 * t) * 2;
                uint32_t ah0 = lds32(ra);
                uint32_t ah1 = lds32(ra + 8 * ROWB);
                uint32_t ah2 = lds32(ra + 16);
                uint32_t ah3 = lds32(ra + 8 * ROWB + 16);
                uint32_t la_ = ra + 64 * ROWB;
                uint32_t al0 = lds32(la_);
                uint32_t al1 = lds32(la_ + 8 * ROWB);
                uint32_t al2 = lds32(la_ + 16);
                uint32_t al3 = lds32(la_ + 8 * ROWB + 16);
#pragma unroll
                for (int nt = 0; nt < 8; ++nt) {
                    mma_bf16(acc[mt][nt], ah0, ah1, ah2, ah3, bh[nt][0], bh[nt][1]);
                    mma_bf16(acc[mt][nt], ah0, ah1, ah2, ah3, bl[nt][0], bl[nt][1]);
                    mma_bf16(acc[mt][nt], al0, al1, al2, al3, bh[nt][0], bh[nt][1]);
                }
            }
        }
        __syncthreads();
    }

    // ---------------- epilogue ----------------
    float* ot = reinterpret_cast<float*>(smem);   // [64][260] fp32, reuses stages
#pragma unroll
    for (int mt = 0; mt < 2; ++mt)
#pragma unroll
        for (int nt = 0; nt < 8; ++nt) {
            int m = wm * 32 + mt * 16 + g;
            int n = wn * 64 + nt * 8 + 2 * t;
            *reinterpret_cast<float2*>(ot + m * 260 + n) =
                make_float2(acc[mt][nt][0], acc[mt][nt][1]);
            *reinterpret_cast<float2*>(ot + (m + 8) * 260 + n) =
                make_float2(acc[mt][nt][2], acc[mt][nt][3]);
        }
    __syncthreads();

    if (tid < 64) {
        const float* pb = reinterpret_cast<const float*>(smem + SM_PAR);
        const float* pg = pb + 256;
        const float* pe = pb + 512;
        const float* pl = pb + 768;
        const float* rowp = ot + tid * 260;
        float h[256];
        float s = 0.f, ss = 0.f;
#pragma unroll 4
        for (int j = 0; j < 256; j += 4) {
            float4 v4 = *reinterpret_cast<const float4*>(rowp + j);
            h[j]     = v4.x + pb[j];
            h[j + 1] = v4.y + pb[j + 1];
            h[j + 2] = v4.z + pb[j + 2];
            h[j + 3] = v4.w + pb[j + 3];
            s += h[j] + h[j + 1] + h[j + 2] + h[j + 3];
            ss += h[j] * h[j] + h[j + 1] * h[j + 1] +
                  h[j + 2] * h[j + 2] + h[j + 3] * h[j + 3];
        }
        float mu = s * (1.f / 256.f);
        float var = ss * (1.f / 256.f) - mu * mu;
        float rs = rsqrtf(var + 1e-5f);
        int row = m0 + tid;
        if (!SECOND) {
            __nv_bfloat16* dh = g_h1h + (size_t)row * FF;
            __nv_bfloat16* dl = g_h1l + (size_t)row * FF;
#pragma unroll 2
            for (int j = 0; j < 256; j += 8) {
                uint32_t wh[4], wl[4];
#pragma unroll
                for (int q = 0; q < 4; ++q) {
                    float y0 = fmaxf(0.f, (h[j + 2 * q] - mu) * rs * pg[j + 2 * q] + pe[j + 2 * q]);
                    float y1 = fmaxf(0.f, (h[j + 2 * q + 1] - mu) * rs * pg[j + 2 * q + 1] + pe[j + 2 * q + 1]);
                    __nv_bfloat16 h0, l0, h1, l1;
                    split_bf16(y0, h0, l0);
                    split_bf16(y1, h1, l1);
                    wh[q] = ((uint32_t)*reinterpret_cast<uint16_t*>(&h1) << 16) |
                            *reinterpret_cast<uint16_t*>(&h0);
                    wl[q] = ((uint32_t)*reinterpret_cast<uint16_t*>(&l1) << 16) |
                            *reinterpret_cast<uint16_t*>(&l0);
                }
                *reinterpret_cast<uint4*>(dh + j) = make_uint4(wh[0], wh[1], wh[2], wh[3]);
                *reinterpret_cast<uint4*>(dl + j) = make_uint4(wl[0], wl[1], wl[2], wl[3]);
            }
        } else {
            float dacc = 0.f;
#pragma unroll 4
            for (int j = 0; j < 256; ++j) {
                float y = fmaxf(0.f, (h[j] - mu) * rs * pg[j] + pe[j]);
                dacc += y * pl[j];
            }
            durout[row] = fmaxf(0.f, dacc + *lbp);
        }
    }
}

// ---------------- launch ----------------
extern "C" void kernel_launch(void* const* d_in, const int* in_sizes, int n_in,
                              void* d_out, int out_size) {
    const float* x   = (const float*)d_in[0];
    const float* c1w = (const float*)d_in[1];
    const float* c1b = (const float*)d_in[2];
    const float* l1g = (const float*)d_in[3];
    const float* l1b = (const float*)d_in[4];
    const float* c2w = (const float*)d_in[5];
    const float* c2b = (const float*)d_in[6];
    const float* l2g = (const float*)d_in[7];
    const float* l2b = (const float*)d_in[8];
    const float* lw  = (const float*)d_in[9];
    const float* lb  = (const float*)d_in[10];
    const int* target = (const int*)d_in[11];
    float* out = (float*)d_out;

    cudaFuncSetAttribute(gemm_ln_kernel<0>, cudaFuncAttributeMaxDynamicSharedMemorySize, SM_TOTAL);
    cudaFuncSetAttribute(gemm_ln_kernel<1>, cudaFuncAttributeMaxDynamicSharedMemorySize, SM_TOTAL);

    prep_w_kernel<<<dim3(256, 2), 256>>>(c1w, c2w);
    im2col_kernel<0><<<NROWS / 8, 256>>>(x);
    build_idx_kernel<<<16, 512>>>(target);
    gemm_ln_kernel<0><<<128, 256, SM_TOTAL>>>(c1b, l1g, l1b, lw, lb, nullptr);
    im2col_kernel<1><<<NROWS / 8, 256>>>(nullptr);
    gemm_ln_kernel<1><<<128, 256, SM_TOTAL>>>(c2b, l2g, l2b, lw, lb, out + OUT_ELEMS);
    gather_kernel<<<NB * MM / 8, 256>>>(x, out);
}